// round 5
// baseline (speedup 1.0000x reference)
#include <cuda_runtime.h>
#include <math.h>

#define NN 50000
#define NE 800000

// ---------------- scratch (device globals: no allocation allowed) ----------
__device__ int   g_is64;
__device__ int   g_deg[NN];
__device__ int   g_off[NN + 1];
__device__ int   g_cur[NN];
__device__ int   g_src[NE];
__device__ __align__(16) float g_w[NE];
__device__ __align__(16) float g_bufA[NN * 256];   // agg128 / agg32 / xl
__device__ __align__(16) float g_bufB[NN * 256];   // xr
__device__ __align__(16) float g_h1[NN * 32];
__device__ __align__(16) float g_h2[NN * 32];
__device__ __align__(16) float g_h3[NN * 256];
__device__ __align__(16) float g_h4[NN * 256];

// Buffer selectors: resolve device-global scratch at compile time. S==-1 -> ext.
template <int S>
__device__ __forceinline__ const float* SB(const float* ext) {
    if constexpr (S == 0) return g_bufA;
    else if constexpr (S == 1) return g_bufB;
    else if constexpr (S == 2) return g_h1;
    else if constexpr (S == 3) return g_h2;
    else if constexpr (S == 4) return g_h3;
    else if constexpr (S == 5) return g_h4;
    else return ext;
}
template <int S>
__device__ __forceinline__ float* SBo(float* ext) {
    if constexpr (S == 0) return g_bufA;
    else if constexpr (S == 1) return g_bufB;
    else if constexpr (S == 2) return g_h1;
    else if constexpr (S == 3) return g_h2;
    else if constexpr (S == 4) return g_h3;
    else if constexpr (S == 5) return g_h4;
    else return ext;
}

// ---------------- helpers ----------------
__device__ __forceinline__ float lrelu(float v) { return v > 0.f ? v : 0.2f * v; }
__device__ __forceinline__ float elu(float v)  { return v > 0.f ? v : __expf(v) - 1.f; }

__device__ __forceinline__ int clampN(int v) {
    return v < 0 ? 0 : (v >= NN ? NN - 1 : v);
}
// Load edge index #pos (element offset in a [2,E] array), dtype-agnostic.
__device__ __forceinline__ int load_idx(const void* ei, size_t pos, int is64) {
    if (is64) return clampN((int)((const long long*)ei)[pos]);
    return clampN(((const int*)ei)[pos]);
}

// ---------------- dtype detection ----------------
// int64 data with values < 2^31: every odd 32-bit word is 0.
// int32 data: odd words are genuine random indices; all-zero is impossible.
__global__ void k_detect(const int* __restrict__ ei32) {
    if (threadIdx.x == 0 && blockIdx.x == 0) {
        int allzero = 1;
        #pragma unroll 1
        for (int i = 0; i < 64; i++)
            if (ei32[2 * i + 1] != 0) { allzero = 0; break; }
        g_is64 = allzero;
    }
}

// ---------------- CSR build ----------------
__global__ void k_zero_deg() {
    int i = blockIdx.x * blockDim.x + threadIdx.x;
    if (i < NN) g_deg[i] = 0;
}

__global__ void k_count(const void* __restrict__ ei) {
    int e = blockIdx.x * blockDim.x + threadIdx.x;
    if (e < NE) {
        int dst = load_idx(ei, (size_t)NE + e, g_is64);
        atomicAdd(&g_deg[dst], 1);
    }
}

__global__ void k_scan() {
    __shared__ int warp_sums[32];
    int t = threadIdx.x;
    int running = 0;
    for (int base = 0; base < NN; base += 1024) {
        int i = base + t;
        int v = (i < NN) ? g_deg[i] : 0;
        int x = v;
        #pragma unroll
        for (int o = 1; o < 32; o <<= 1) {
            int y = __shfl_up_sync(0xffffffffu, x, o);
            if ((t & 31) >= o) x += y;
        }
        if ((t & 31) == 31) warp_sums[t >> 5] = x;
        __syncthreads();
        if (t < 32) {
            int w = warp_sums[t];
            #pragma unroll
            for (int o = 1; o < 32; o <<= 1) {
                int y = __shfl_up_sync(0xffffffffu, w, o);
                if (t >= o) w += y;
            }
            warp_sums[t] = w;
        }
        __syncthreads();
        int warp_prefix = (t >= 32) ? warp_sums[(t >> 5) - 1] : 0;
        int excl = x + warp_prefix - v;
        if (i < NN) { g_off[i] = running + excl; g_cur[i] = running + excl; }
        int block_total = warp_sums[31];
        __syncthreads();
        running += block_total;
    }
    if (t == 0) g_off[NN] = running;
}

__global__ void k_scatter(const void* __restrict__ ei, const float* __restrict__ ea) {
    int e = blockIdx.x * blockDim.x + threadIdx.x;
    if (e < NE) {
        int is64 = g_is64;
        int s = load_idx(ei, (size_t)e, is64);
        int d = load_idx(ei, (size_t)NE + e, is64);
        int p = atomicAdd(&g_cur[d], 1);
        if (p >= 0 && p < NE) {
            g_src[p] = s;
            g_w[p]   = ea[e];
        }
    }
}

// ---------------- GraphConv max aggregation (warp per node) ----------------
// F=128: input ext (x). F=32: input g_h1. Output always g_bufA.
template <int F, int XSEL>
__global__ void k_gc_agg(const float* __restrict__ xext) {
    const float* __restrict__ x = SB<XSEL>(xext);
    float* __restrict__ agg = g_bufA;
    int node = (blockIdx.x * blockDim.x + threadIdx.x) >> 5;
    int lane = threadIdx.x & 31;
    if (node >= NN) return;
    int beg = g_off[node], end = g_off[node + 1];
    if constexpr (F == 128) {
        float4 mx = make_float4(-INFINITY, -INFINITY, -INFINITY, -INFINITY);
        int j = beg;
        for (; j + 1 < end; j += 2) {
            int   s0 = g_src[j],     s1 = g_src[j + 1];
            float w0 = g_w[j],       w1 = g_w[j + 1];
            float4 v0 = *(const float4*)&x[(size_t)s0 * 128 + lane * 4];
            float4 v1 = *(const float4*)&x[(size_t)s1 * 128 + lane * 4];
            mx.x = fmaxf(mx.x, fmaxf(v0.x * w0, v1.x * w1));
            mx.y = fmaxf(mx.y, fmaxf(v0.y * w0, v1.y * w1));
            mx.z = fmaxf(mx.z, fmaxf(v0.z * w0, v1.z * w1));
            mx.w = fmaxf(mx.w, fmaxf(v0.w * w0, v1.w * w1));
        }
        if (j < end) {
            int s = g_src[j];
            float w = g_w[j];
            float4 v = *(const float4*)&x[(size_t)s * 128 + lane * 4];
            mx.x = fmaxf(mx.x, v.x * w);
            mx.y = fmaxf(mx.y, v.y * w);
            mx.z = fmaxf(mx.z, v.z * w);
            mx.w = fmaxf(mx.w, v.w * w);
        }
        if (beg == end) mx = make_float4(0.f, 0.f, 0.f, 0.f);
        *(float4*)&agg[(size_t)node * 128 + lane * 4] = mx;
    } else {  // F == 32
        float mx = -INFINITY;
        int j = beg;
        for (; j + 1 < end; j += 2) {
            int   s0 = g_src[j],     s1 = g_src[j + 1];
            float w0 = g_w[j],       w1 = g_w[j + 1];
            float a = x[(size_t)s0 * 32 + lane] * w0;
            float b = x[(size_t)s1 * 32 + lane] * w1;
            mx = fmaxf(mx, fmaxf(a, b));
        }
        if (j < end) mx = fmaxf(mx, x[(size_t)g_src[j] * 32 + lane] * g_w[j]);
        agg[(size_t)node * 32 + lane] = (beg == end) ? 0.f : mx;
    }
}

// ---------------- GEMM, N-out = 32 (optional dual-A, optional relu) -------
// C[M,32] = act(A1@B1 (+ A2@B2) + bias). 128 threads, BM=128, BK=32.
template <int K, int A1SEL, bool DUAL, int A2SEL, bool RELU, int CSEL>
__global__ __launch_bounds__(128)
void k_gemm_n32(const float* __restrict__ A1e, const float* __restrict__ B1,
                const float* __restrict__ A2e, const float* __restrict__ B2,
                const float* __restrict__ bias, float* __restrict__ Ce, int M) {
    const float* __restrict__ A1 = SB<A1SEL>(A1e);
    const float* __restrict__ A2 = SB<A2SEL>(A2e);
    float* __restrict__ C = SBo<CSEL>(Ce);

    __shared__ float As[32][128];
    __shared__ float A2s[32][128];
    __shared__ float Bs[32][32];
    __shared__ float B2s[32][32];

    int t  = threadIdx.x;
    int m0 = blockIdx.x * 128;
    int j0 = (t & 7) * 4;
    int r0 = (t >> 3) * 8;

    float acc[8][4];
    #pragma unroll
    for (int i = 0; i < 8; i++)
        #pragma unroll
        for (int c = 0; c < 4; c++) acc[i][c] = 0.f;

    for (int kb = 0; kb < K; kb += 32) {
        #pragma unroll
        for (int l = 0; l < 8; l++) {
            int slot = t + l * 128;       // 0..1023 float4 slots
            int m = slot >> 3;
            int kq = slot & 7;
            int row = m0 + m;
            float4 v = make_float4(0.f, 0.f, 0.f, 0.f);
            if (row < M) v = *(const float4*)&A1[(size_t)row * K + kb + kq * 4];
            As[kq * 4 + 0][m] = v.x; As[kq * 4 + 1][m] = v.y;
            As[kq * 4 + 2][m] = v.z; As[kq * 4 + 3][m] = v.w;
            if constexpr (DUAL) {
                float4 v2 = make_float4(0.f, 0.f, 0.f, 0.f);
                if (row < M) v2 = *(const float4*)&A2[(size_t)row * K + kb + kq * 4];
                A2s[kq * 4 + 0][m] = v2.x; A2s[kq * 4 + 1][m] = v2.y;
                A2s[kq * 4 + 2][m] = v2.z; A2s[kq * 4 + 3][m] = v2.w;
            }
        }
        #pragma unroll
        for (int l = 0; l < 2; l++) {
            int slot = t + l * 128;       // 0..255 float4 slots
            int k = slot >> 3;
            int jq = slot & 7;
            *(float4*)&Bs[k][jq * 4] = *(const float4*)&B1[(size_t)(kb + k) * 32 + jq * 4];
            if constexpr (DUAL)
                *(float4*)&B2s[k][jq * 4] = *(const float4*)&B2[(size_t)(kb + k) * 32 + jq * 4];
        }
        __syncthreads();

        #pragma unroll
        for (int kk = 0; kk < 32; kk++) {
            float av[8], bv[4];
            *(float4*)&av[0] = *(float4*)&As[kk][r0];
            *(float4*)&av[4] = *(float4*)&As[kk][r0 + 4];
            *(float4*)&bv[0] = *(float4*)&Bs[kk][j0];
            #pragma unroll
            for (int i = 0; i < 8; i++)
                #pragma unroll
                for (int c = 0; c < 4; c++) acc[i][c] += av[i] * bv[c];
            if constexpr (DUAL) {
                float av2[8], bv2[4];
                *(float4*)&av2[0] = *(float4*)&A2s[kk][r0];
                *(float4*)&av2[4] = *(float4*)&A2s[kk][r0 + 4];
                *(float4*)&bv2[0] = *(float4*)&B2s[kk][j0];
                #pragma unroll
                for (int i = 0; i < 8; i++)
                    #pragma unroll
                    for (int c = 0; c < 4; c++) acc[i][c] += av2[i] * bv2[c];
            }
        }
        __syncthreads();
    }

    float bv[4];
    *(float4*)&bv[0] = *(const float4*)&bias[j0];
    #pragma unroll
    for (int i = 0; i < 8; i++) {
        int row = m0 + r0 + i;
        if (row < M) {
            float o[4];
            #pragma unroll
            for (int c = 0; c < 4; c++) {
                float v = acc[i][c] + bv[c];
                if constexpr (RELU) v = fmaxf(v, 0.f);
                o[c] = v;
            }
            *(float4*)&C[(size_t)row * 32 + j0] = *(float4*)&o[0];
        }
    }
}

// ---------------- GEMM, N-out = 256, computes xl (z=0) and xr (z=1) -------
// A from scratch (ASEL), outputs fixed: Cl=g_bufA, Cr=g_bufB.
// BM=128, BN=128, BK=8, 256 threads, 8x8 micro-tile.
template <int K, int ASEL>
__global__ __launch_bounds__(256)
void k_gemm_n256(const float* __restrict__ Bl, const float* __restrict__ biasl,
                 const float* __restrict__ Br, const float* __restrict__ biasr,
                 int M) {
    const float* __restrict__ A = SB<ASEL>((const float*)0);
    const float* B    = blockIdx.z ? Br : Bl;
    const float* bias = blockIdx.z ? biasr : biasl;
    float* C          = blockIdx.z ? g_bufB : g_bufA;

    __shared__ float As[8][128];
    __shared__ float Bs[8][128];

    int t  = threadIdx.x;
    int m0 = blockIdx.y * 128;
    int n0 = blockIdx.x * 128;
    int tx = t & 15, ty = t >> 4;
    int lm = t >> 1, lkq = t & 1;
    int lk = t >> 5, lj = t & 31;

    float acc[8][8];
    #pragma unroll
    for (int i = 0; i < 8; i++)
        #pragma unroll
        for (int j = 0; j < 8; j++) acc[i][j] = 0.f;

    for (int kb = 0; kb < K; kb += 8) {
        float4 va = make_float4(0.f, 0.f, 0.f, 0.f);
        int row = m0 + lm;
        if (row < M) va = *(const float4*)&A[(size_t)row * K + kb + lkq * 4];
        As[lkq * 4 + 0][lm] = va.x; As[lkq * 4 + 1][lm] = va.y;
        As[lkq * 4 + 2][lm] = va.z; As[lkq * 4 + 3][lm] = va.w;
        *(float4*)&Bs[lk][lj * 4] = *(const float4*)&B[(size_t)(kb + lk) * 256 + n0 + lj * 4];
        __syncthreads();

        #pragma unroll
        for (int kk = 0; kk < 8; kk++) {
            float av[8], bv[8];
            *(float4*)&av[0] = *(float4*)&As[kk][ty * 8];
            *(float4*)&av[4] = *(float4*)&As[kk][ty * 8 + 4];
            *(float4*)&bv[0] = *(float4*)&Bs[kk][tx * 8];
            *(float4*)&bv[4] = *(float4*)&Bs[kk][tx * 8 + 4];
            #pragma unroll
            for (int i = 0; i < 8; i++)
                #pragma unroll
                for (int j = 0; j < 8; j++) acc[i][j] += av[i] * bv[j];
        }
        __syncthreads();
    }

    float bv[8];
    *(float4*)&bv[0] = *(const float4*)&bias[n0 + tx * 8];
    *(float4*)&bv[4] = *(const float4*)&bias[n0 + tx * 8 + 4];
    #pragma unroll
    for (int i = 0; i < 8; i++) {
        int row = m0 + ty * 8 + i;
        if (row < M) {
            float o[8];
            #pragma unroll
            for (int j = 0; j < 8; j++) o[j] = acc[i][j] + bv[j];
            *(float4*)&C[(size_t)row * 256 + n0 + tx * 8]     = *(float4*)&o[0];
            *(float4*)&C[(size_t)row * 256 + n0 + tx * 8 + 4] = *(float4*)&o[4];
        }
    }
}

// ---------------- GATv2: warp per node, online softmax --------------------
// xl=g_bufA, xr=g_bufB; output selected at compile time (g_h3 / g_h4).
// lane l owns head = l/4, channels (l%4)*8 .. +8 (8 consecutive floats).
template <int OSEL>
__global__ void k_gat(const float* __restrict__ att, const float* __restrict__ bias) {
    const float* __restrict__ xl = g_bufA;
    const float* __restrict__ xr = g_bufB;
    float* __restrict__ out = SBo<OSEL>((float*)0);

    int node = (blockIdx.x * blockDim.x + threadIdx.x) >> 5;
    int lane = threadIdx.x & 31;
    if (node >= NN) return;
    int base = (lane >> 2) * 32 + (lane & 3) * 8;

    float4 at0 = *(const float4*)&att[base];
    float4 at1 = *(const float4*)&att[base + 4];
    float4 xr0 = *(const float4*)&xr[(size_t)node * 256 + base];
    float4 xr1 = *(const float4*)&xr[(size_t)node * 256 + base + 4];

    float m = -INFINITY, d = 0.f;
    float4 acc0 = make_float4(0.f, 0.f, 0.f, 0.f);
    float4 acc1 = make_float4(0.f, 0.f, 0.f, 0.f);

    int beg = g_off[node], end = g_off[node + 1];
    int nxt = (beg < end) ? g_src[beg] : node;        // prefetch first src
    for (int j = beg; j <= end; j++) {                 // j==end -> self-loop
        int s = nxt;
        nxt = (j + 1 < end) ? g_src[j + 1] : node;    // prefetch next src
        float4 v0 = *(const float4*)&xl[(size_t)s * 256 + base];
        float4 v1 = *(const float4*)&xl[(size_t)s * 256 + base + 4];
        float sc = at0.x * lrelu(v0.x + xr0.x) + at0.y * lrelu(v0.y + xr0.y)
                 + at0.z * lrelu(v0.z + xr0.z) + at0.w * lrelu(v0.w + xr0.w)
                 + at1.x * lrelu(v1.x + xr1.x) + at1.y * lrelu(v1.y + xr1.y)
                 + at1.z * lrelu(v1.z + xr1.z) + at1.w * lrelu(v1.w + xr1.w);
        sc += __shfl_xor_sync(0xffffffffu, sc, 1);
        sc += __shfl_xor_sync(0xffffffffu, sc, 2);
        if (sc > m) {
            float r = __expf(m - sc);                  // m=-inf -> r=0
            d *= r;
            acc0.x *= r; acc0.y *= r; acc0.z *= r; acc0.w *= r;
            acc1.x *= r; acc1.y *= r; acc1.z *= r; acc1.w *= r;
            m = sc;
        }
        float p = __expf(sc - m);
        d += p;
        acc0.x += p * v0.x; acc0.y += p * v0.y; acc0.z += p * v0.z; acc0.w += p * v0.w;
        acc1.x += p * v1.x; acc1.y += p * v1.y; acc1.z += p * v1.z; acc1.w += p * v1.w;
    }

    float inv = 1.f / d;
    float4 b0 = *(const float4*)&bias[base];
    float4 b1 = *(const float4*)&bias[base + 4];
    float4 o0, o1;
    o0.x = elu(acc0.x * inv + b0.x); o0.y = elu(acc0.y * inv + b0.y);
    o0.z = elu(acc0.z * inv + b0.z); o0.w = elu(acc0.w * inv + b0.w);
    o1.x = elu(acc1.x * inv + b1.x); o1.y = elu(acc1.y * inv + b1.y);
    o1.z = elu(acc1.z * inv + b1.z); o1.w = elu(acc1.w * inv + b1.w);
    *(float4*)&out[(size_t)node * 256 + base]     = o0;
    *(float4*)&out[(size_t)node * 256 + base + 4] = o1;
}

// ---------------- launch ----------------
extern "C" void kernel_launch(void* const* d_in, const int* in_sizes, int n_in,
                              void* d_out, int out_size) {
    const float* x       = (const float*)d_in[0];
    const void*  ei      = d_in[1];                    // int32 or int64, detected on device
    const float* ea      = (const float*)d_in[2];
    const float* W_rel1  = (const float*)d_in[3];
    const float* b_rel1  = (const float*)d_in[4];
    const float* W_root1 = (const float*)d_in[5];
    const float* W_rel2  = (const float*)d_in[6];
    const float* b_rel2  = (const float*)d_in[7];
    const float* W_root2 = (const float*)d_in[8];
    const float* Wl1     = (const float*)d_in[9];
    const float* bl1     = (const float*)d_in[10];
    const float* Wr1     = (const float*)d_in[11];
    const float* br1     = (const float*)d_in[12];
    const float* att1    = (const float*)d_in[13];
    const float* bias1   = (const float*)d_in[14];
    const float* Wl2     = (const float*)d_in[15];
    const float* bl2     = (const float*)d_in[16];
    const float* Wr2     = (const float*)d_in[17];
    const float* br2     = (const float*)d_in[18];
    const float* att2    = (const float*)d_in[19];
    const float* bias2   = (const float*)d_in[20];
    const float* W_lin   = (const float*)d_in[21];
    const float* b_lin   = (const float*)d_in[22];
    float*       out     = (float*)d_out;

    const int M = NN;
    dim3 g256(2, (M + 127) / 128, 2);

    // dtype detection + CSR build
    k_detect<<<1, 32>>>((const int*)ei);
    k_zero_deg<<<(NN + 255) / 256, 256>>>();
    k_count<<<(NE + 255) / 256, 256>>>(ei);
    k_scan<<<1, 1024>>>();
    k_scatter<<<(NE + 255) / 256, 256>>>(ei, ea);

    // GraphConv 1: agg(x) -> g_bufA; h1 = relu(g_bufA@W_rel1 + x@W_root1 + b)
    k_gc_agg<128, -1><<<(NN + 7) / 8, 256>>>(x);
    k_gemm_n32<128, 0, true, -1, true, 2><<<(M + 127) / 128, 128>>>(
        (const float*)0, W_rel1, x, W_root1, b_rel1, (float*)0, M);

    // GraphConv 2: agg(h1) -> g_bufA; h2 = relu(g_bufA@W_rel2 + h1@W_root2 + b)
    k_gc_agg<32, 2><<<(NN + 7) / 8, 256>>>((const float*)0);
    k_gemm_n32<32, 0, true, 2, true, 3><<<(M + 127) / 128, 128>>>(
        (const float*)0, W_rel2, (const float*)0, W_root2, b_rel2, (float*)0, M);

    // GATv2 1: xl/xr from h2; h3 = elu(gat)
    k_gemm_n256<32, 3><<<g256, 256>>>(Wl1, bl1, Wr1, br1, M);
    k_gat<4><<<(NN + 7) / 8, 256>>>(att1, bias1);

    // GATv2 2: xl/xr from h3; h4 = elu(gat)
    k_gemm_n256<256, 4><<<g256, 256>>>(Wl2, bl2, Wr2, br2, M);
    k_gat<5><<<(NN + 7) / 8, 256>>>(att2, bias2);

    // Final linear: out = h4 @ W_lin + b_lin
    k_gemm_n32<256, 5, false, -1, false, -1><<<(M + 127) / 128, 128>>>(
        (const float*)0, W_lin, (const float*)0, (const float*)0, b_lin, out, M);
}

// round 8
// speedup vs baseline: 1.0842x; 1.0842x over previous
#include <cuda_runtime.h>
#include <math.h>

#define NN 50000
#define NE 800000
#define SCAN_CHUNK 4096
#define NBLK ((NN + SCAN_CHUNK - 1) / SCAN_CHUNK)   // 13

// ---------------- scratch (device globals: no allocation allowed) ----------
__device__ int   g_is64;
__device__ int   g_deg[NN];
__device__ int   g_off[NN + 1];
__device__ int   g_cur[NN];
__device__ int   g_bsum[NBLK];
__device__ int   g_bpre[NBLK];
__device__ int   g_src[NE];
__device__ __align__(16) float g_w[NE];
__device__ __align__(16) float g_bufA[NN * 256];   // agg128 / agg32 / xl
__device__ __align__(16) float g_bufB[NN * 256];   // xr
__device__ __align__(16) float g_h1[NN * 32];
__device__ __align__(16) float g_h2[NN * 32];
__device__ __align__(16) float g_h3[NN * 256];
__device__ __align__(16) float g_h4[NN * 256];

// Buffer selectors: resolve device-global scratch at compile time. S==-1 -> ext.
template <int S>
__device__ __forceinline__ const float* SB(const float* ext) {
    if constexpr (S == 0) return g_bufA;
    else if constexpr (S == 1) return g_bufB;
    else if constexpr (S == 2) return g_h1;
    else if constexpr (S == 3) return g_h2;
    else if constexpr (S == 4) return g_h3;
    else if constexpr (S == 5) return g_h4;
    else return ext;
}
template <int S>
__device__ __forceinline__ float* SBo(float* ext) {
    if constexpr (S == 0) return g_bufA;
    else if constexpr (S == 1) return g_bufB;
    else if constexpr (S == 2) return g_h1;
    else if constexpr (S == 3) return g_h2;
    else if constexpr (S == 4) return g_h3;
    else if constexpr (S == 5) return g_h4;
    else return ext;
}

// ---------------- helpers ----------------
__device__ __forceinline__ float lrelu(float v) { return v > 0.f ? v : 0.2f * v; }
__device__ __forceinline__ float elu(float v)  { return v > 0.f ? v : __expf(v) - 1.f; }

__device__ __forceinline__ int clampN(int v) {
    return v < 0 ? 0 : (v >= NN ? NN - 1 : v);
}
// Load edge index #pos (element offset in a [2,E] array), dtype-agnostic.
__device__ __forceinline__ int load_idx(const void* ei, size_t pos, int is64) {
    if (is64) return clampN((int)((const long long*)ei)[pos]);
    return clampN(((const int*)ei)[pos]);
}

// ---------------- dtype detection ----------------
__global__ void k_detect(const int* __restrict__ ei32) {
    if (threadIdx.x == 0 && blockIdx.x == 0) {
        int allzero = 1;
        #pragma unroll 1
        for (int i = 0; i < 64; i++)
            if (ei32[2 * i + 1] != 0) { allzero = 0; break; }
        g_is64 = allzero;
    }
}

// ---------------- CSR build ----------------
__global__ void k_zero_deg() {
    int i = blockIdx.x * blockDim.x + threadIdx.x;
    if (i < NN) g_deg[i] = 0;
}

__global__ void k_count(const void* __restrict__ ei) {
    int e = blockIdx.x * blockDim.x + threadIdx.x;
    if (e < NE) {
        int dst = load_idx(ei, (size_t)NE + e, g_is64);
        atomicAdd(&g_deg[dst], 1);
    }
}

// --- multi-block scan: phase 1 (per-block local exclusive scan + block sum)
__global__ __launch_bounds__(1024) void k_scan_local() {
    __shared__ int ws[32];
    int b = blockIdx.x, t = threadIdx.x;
    int base = b * SCAN_CHUNK + t * 4;
    int v[4];
    #pragma unroll
    for (int c = 0; c < 4; c++) v[c] = (base + c < NN) ? g_deg[base + c] : 0;
    int s = v[0] + v[1] + v[2] + v[3];
    // block-wide inclusive scan of per-thread sums
    int x = s;
    #pragma unroll
    for (int o = 1; o < 32; o <<= 1) {
        int y = __shfl_up_sync(0xffffffffu, x, o);
        if ((t & 31) >= o) x += y;
    }
    if ((t & 31) == 31) ws[t >> 5] = x;
    __syncthreads();
    if (t < 32) {
        int w = ws[t];
        #pragma unroll
        for (int o = 1; o < 32; o <<= 1) {
            int y = __shfl_up_sync(0xffffffffu, w, o);
            if (t >= o) w += y;
        }
        ws[t] = w;
    }
    __syncthreads();
    int incl = x + ((t >= 32) ? ws[(t >> 5) - 1] : 0);
    int run = incl - s;   // exclusive prefix for this thread's first element
    #pragma unroll
    for (int c = 0; c < 4; c++) {
        if (base + c < NN) g_off[base + c] = run;
        run += v[c];
    }
    if (t == 1023) g_bsum[b] = incl;
}

// --- phase 2: scan the 13 block sums (single warp)
__global__ void k_scan_bsum() {
    int t = threadIdx.x;
    int v = (t < NBLK) ? g_bsum[t] : 0;
    int x = v;
    #pragma unroll
    for (int o = 1; o < 32; o <<= 1) {
        int y = __shfl_up_sync(0xffffffffu, x, o);
        if (t >= o) x += y;
    }
    if (t < NBLK) g_bpre[t] = x - v;
    if (t == 31) g_off[NN] = x;   // total (lanes >= NBLK contribute 0)
}

// --- phase 3: add block prefixes, fill g_cur
__global__ void k_scan_add() {
    int i = blockIdx.x * blockDim.x + threadIdx.x;
    if (i < NN) {
        int o = g_off[i] + g_bpre[i / SCAN_CHUNK];
        g_off[i] = o;
        g_cur[i] = o;
    }
}

__global__ void k_scatter(const void* __restrict__ ei, const float* __restrict__ ea) {
    int e = blockIdx.x * blockDim.x + threadIdx.x;
    if (e < NE) {
        int is64 = g_is64;
        int s = load_idx(ei, (size_t)e, is64);
        int d = load_idx(ei, (size_t)NE + e, is64);
        int p = atomicAdd(&g_cur[d], 1);
        if (p >= 0 && p < NE) {
            g_src[p] = s;
            g_w[p]   = ea[e];
        }
    }
}

// ---------------- GraphConv max aggregation (warp per node, unroll-4) ------
template <int F, int XSEL>
__global__ void k_gc_agg(const float* __restrict__ xext) {
    const float* __restrict__ x = SB<XSEL>(xext);
    float* __restrict__ agg = g_bufA;
    int node = (blockIdx.x * blockDim.x + threadIdx.x) >> 5;
    int lane = threadIdx.x & 31;
    if (node >= NN) return;
    int beg = g_off[node], end = g_off[node + 1];
    if constexpr (F == 128) {
        float4 mx = make_float4(-INFINITY, -INFINITY, -INFINITY, -INFINITY);
        int j = beg;
        for (; j + 3 < end; j += 4) {
            int   s0 = g_src[j],   s1 = g_src[j+1], s2 = g_src[j+2], s3 = g_src[j+3];
            float w0 = g_w[j],     w1 = g_w[j+1],   w2 = g_w[j+2],   w3 = g_w[j+3];
            float4 v0 = *(const float4*)&x[(size_t)s0 * 128 + lane * 4];
            float4 v1 = *(const float4*)&x[(size_t)s1 * 128 + lane * 4];
            float4 v2 = *(const float4*)&x[(size_t)s2 * 128 + lane * 4];
            float4 v3 = *(const float4*)&x[(size_t)s3 * 128 + lane * 4];
            mx.x = fmaxf(mx.x, fmaxf(fmaxf(v0.x*w0, v1.x*w1), fmaxf(v2.x*w2, v3.x*w3)));
            mx.y = fmaxf(mx.y, fmaxf(fmaxf(v0.y*w0, v1.y*w1), fmaxf(v2.y*w2, v3.y*w3)));
            mx.z = fmaxf(mx.z, fmaxf(fmaxf(v0.z*w0, v1.z*w1), fmaxf(v2.z*w2, v3.z*w3)));
            mx.w = fmaxf(mx.w, fmaxf(fmaxf(v0.w*w0, v1.w*w1), fmaxf(v2.w*w2, v3.w*w3)));
        }
        for (; j < end; j++) {
            int s = g_src[j];
            float w = g_w[j];
            float4 v = *(const float4*)&x[(size_t)s * 128 + lane * 4];
            mx.x = fmaxf(mx.x, v.x * w);
            mx.y = fmaxf(mx.y, v.y * w);
            mx.z = fmaxf(mx.z, v.z * w);
            mx.w = fmaxf(mx.w, v.w * w);
        }
        if (beg == end) mx = make_float4(0.f, 0.f, 0.f, 0.f);
        *(float4*)&agg[(size_t)node * 128 + lane * 4] = mx;
    } else {  // F == 32
        float mx = -INFINITY;
        int j = beg;
        for (; j + 3 < end; j += 4) {
            int   s0 = g_src[j],   s1 = g_src[j+1], s2 = g_src[j+2], s3 = g_src[j+3];
            float w0 = g_w[j],     w1 = g_w[j+1],   w2 = g_w[j+2],   w3 = g_w[j+3];
            float a = x[(size_t)s0 * 32 + lane] * w0;
            float b = x[(size_t)s1 * 32 + lane] * w1;
            float c = x[(size_t)s2 * 32 + lane] * w2;
            float d = x[(size_t)s3 * 32 + lane] * w3;
            mx = fmaxf(mx, fmaxf(fmaxf(a, b), fmaxf(c, d)));
        }
        for (; j < end; j++) mx = fmaxf(mx, x[(size_t)g_src[j] * 32 + lane] * g_w[j]);
        agg[(size_t)node * 32 + lane] = (beg == end) ? 0.f : mx;
    }
}

// ---------------- GEMM, N-out = 32 (optional dual-A, optional relu) -------
template <int K, int A1SEL, bool DUAL, int A2SEL, bool RELU, int CSEL>
__global__ __launch_bounds__(128)
void k_gemm_n32(const float* __restrict__ A1e, const float* __restrict__ B1,
                const float* __restrict__ A2e, const float* __restrict__ B2,
                const float* __restrict__ bias, float* __restrict__ Ce, int M) {
    const float* __restrict__ A1 = SB<A1SEL>(A1e);
    const float* __restrict__ A2 = SB<A2SEL>(A2e);
    float* __restrict__ C = SBo<CSEL>(Ce);

    __shared__ float As[32][128];
    __shared__ float A2s[32][128];
    __shared__ float Bs[32][32];
    __shared__ float B2s[32][32];

    int t  = threadIdx.x;
    int m0 = blockIdx.x * 128;
    int j0 = (t & 7) * 4;
    int r0 = (t >> 3) * 8;

    float acc[8][4];
    #pragma unroll
    for (int i = 0; i < 8; i++)
        #pragma unroll
        for (int c = 0; c < 4; c++) acc[i][c] = 0.f;

    for (int kb = 0; kb < K; kb += 32) {
        #pragma unroll
        for (int l = 0; l < 8; l++) {
            int slot = t + l * 128;
            int m = slot >> 3;
            int kq = slot & 7;
            int row = m0 + m;
            float4 v = make_float4(0.f, 0.f, 0.f, 0.f);
            if (row < M) v = *(const float4*)&A1[(size_t)row * K + kb + kq * 4];
            As[kq * 4 + 0][m] = v.x; As[kq * 4 + 1][m] = v.y;
            As[kq * 4 + 2][m] = v.z; As[kq * 4 + 3][m] = v.w;
            if constexpr (DUAL) {
                float4 v2 = make_float4(0.f, 0.f, 0.f, 0.f);
                if (row < M) v2 = *(const float4*)&A2[(size_t)row * K + kb + kq * 4];
                A2s[kq * 4 + 0][m] = v2.x; A2s[kq * 4 + 1][m] = v2.y;
                A2s[kq * 4 + 2][m] = v2.z; A2s[kq * 4 + 3][m] = v2.w;
            }
        }
        #pragma unroll
        for (int l = 0; l < 2; l++) {
            int slot = t + l * 128;
            int k = slot >> 3;
            int jq = slot & 7;
            *(float4*)&Bs[k][jq * 4] = *(const float4*)&B1[(size_t)(kb + k) * 32 + jq * 4];
            if constexpr (DUAL)
                *(float4*)&B2s[k][jq * 4] = *(const float4*)&B2[(size_t)(kb + k) * 32 + jq * 4];
        }
        __syncthreads();

        #pragma unroll
        for (int kk = 0; kk < 32; kk++) {
            float av[8], bv[4];
            *(float4*)&av[0] = *(float4*)&As[kk][r0];
            *(float4*)&av[4] = *(float4*)&As[kk][r0 + 4];
            *(float4*)&bv[0] = *(float4*)&Bs[kk][j0];
            #pragma unroll
            for (int i = 0; i < 8; i++)
                #pragma unroll
                for (int c = 0; c < 4; c++) acc[i][c] += av[i] * bv[c];
            if constexpr (DUAL) {
                float av2[8], bv2[4];
                *(float4*)&av2[0] = *(float4*)&A2s[kk][r0];
                *(float4*)&av2[4] = *(float4*)&A2s[kk][r0 + 4];
                *(float4*)&bv2[0] = *(float4*)&B2s[kk][j0];
                #pragma unroll
                for (int i = 0; i < 8; i++)
                    #pragma unroll
                    for (int c = 0; c < 4; c++) acc[i][c] += av2[i] * bv2[c];
            }
        }
        __syncthreads();
    }

    float bv[4];
    *(float4*)&bv[0] = *(const float4*)&bias[j0];
    #pragma unroll
    for (int i = 0; i < 8; i++) {
        int row = m0 + r0 + i;
        if (row < M) {
            float o[4];
            #pragma unroll
            for (int c = 0; c < 4; c++) {
                float v = acc[i][c] + bv[c];
                if constexpr (RELU) v = fmaxf(v, 0.f);
                o[c] = v;
            }
            *(float4*)&C[(size_t)row * 32 + j0] = *(float4*)&o[0];
        }
    }
}

// ---------------- GEMM, N-out = 256, computes xl (z=0) and xr (z=1) -------
template <int K, int ASEL>
__global__ __launch_bounds__(256)
void k_gemm_n256(const float* __restrict__ Bl, const float* __restrict__ biasl,
                 const float* __restrict__ Br, const float* __restrict__ biasr,
                 int M) {
    const float* __restrict__ A = SB<ASEL>((const float*)0);
    const float* B    = blockIdx.z ? Br : Bl;
    const float* bias = blockIdx.z ? biasr : biasl;
    float* C          = blockIdx.z ? g_bufB : g_bufA;

    __shared__ float As[8][128];
    __shared__ float Bs[8][128];

    int t  = threadIdx.x;
    int m0 = blockIdx.y * 128;
    int n0 = blockIdx.x * 128;
    int tx = t & 15, ty = t >> 4;
    int lm = t >> 1, lkq = t & 1;
    int lk = t >> 5, lj = t & 31;

    float acc[8][8];
    #pragma unroll
    for (int i = 0; i < 8; i++)
        #pragma unroll
        for (int j = 0; j < 8; j++) acc[i][j] = 0.f;

    for (int kb = 0; kb < K; kb += 8) {
        float4 va = make_float4(0.f, 0.f, 0.f, 0.f);
        int row = m0 + lm;
        if (row < M) va = *(const float4*)&A[(size_t)row * K + kb + lkq * 4];
        As[lkq * 4 + 0][lm] = va.x; As[lkq * 4 + 1][lm] = va.y;
        As[lkq * 4 + 2][lm] = va.z; As[lkq * 4 + 3][lm] = va.w;
        *(float4*)&Bs[lk][lj * 4] = *(const float4*)&B[(size_t)(kb + lk) * 256 + n0 + lj * 4];
        __syncthreads();

        #pragma unroll
        for (int kk = 0; kk < 8; kk++) {
            float av[8], bv[8];
            *(float4*)&av[0] = *(float4*)&As[kk][ty * 8];
            *(float4*)&av[4] = *(float4*)&As[kk][ty * 8 + 4];
            *(float4*)&bv[0] = *(float4*)&Bs[kk][tx * 8];
            *(float4*)&bv[4] = *(float4*)&Bs[kk][tx * 8 + 4];
            #pragma unroll
            for (int i = 0; i < 8; i++)
                #pragma unroll
                for (int j = 0; j < 8; j++) acc[i][j] += av[i] * bv[j];
        }
        __syncthreads();
    }

    float bv[8];
    *(float4*)&bv[0] = *(const float4*)&bias[n0 + tx * 8];
    *(float4*)&bv[4] = *(const float4*)&bias[n0 + tx * 8 + 4];
    #pragma unroll
    for (int i = 0; i < 8; i++) {
        int row = m0 + ty * 8 + i;
        if (row < M) {
            float o[8];
            #pragma unroll
            for (int j = 0; j < 8; j++) o[j] = acc[i][j] + bv[j];
            *(float4*)&C[(size_t)row * 256 + n0 + tx * 8]     = *(float4*)&o[0];
            *(float4*)&C[(size_t)row * 256 + n0 + tx * 8 + 4] = *(float4*)&o[4];
        }
    }
}

// ---------------- GATv2: warp per node, 2-edge branch-free online softmax --
// xl=g_bufA, xr=g_bufB; output selected at compile time (g_h3 / g_h4).
// lane l owns head = l/4, channels (l%4)*8 .. +8.
template <int OSEL>
__global__ void k_gat(const float* __restrict__ att, const float* __restrict__ bias) {
    const float* __restrict__ xl = g_bufA;
    const float* __restrict__ xr = g_bufB;
    float* __restrict__ out = SBo<OSEL>((float*)0);

    int node = (blockIdx.x * blockDim.x + threadIdx.x) >> 5;
    int lane = threadIdx.x & 31;
    if (node >= NN) return;
    int base = (lane >> 2) * 32 + (lane & 3) * 8;

    float4 at0 = *(const float4*)&att[base];
    float4 at1 = *(const float4*)&att[base + 4];
    float4 xr0 = *(const float4*)&xr[(size_t)node * 256 + base];
    float4 xr1 = *(const float4*)&xr[(size_t)node * 256 + base + 4];

    float m = -INFINITY, d = 0.f;
    float4 acc0 = make_float4(0.f, 0.f, 0.f, 0.f);
    float4 acc1 = make_float4(0.f, 0.f, 0.f, 0.f);

    int beg = g_off[node], end = g_off[node + 1];
    int T = end - beg + 1;                 // +1 virtual self-loop at position end
    int t = 0;
    for (; t + 1 < T; t += 2) {
        int i0 = beg + t, i1 = beg + t + 1;
        int s0 = g_src[i0];                // i0 < end guaranteed (t < T-1)
        int s1 = (i1 < end) ? g_src[i1] : node;
        float4 a0 = *(const float4*)&xl[(size_t)s0 * 256 + base];
        float4 a1 = *(const float4*)&xl[(size_t)s0 * 256 + base + 4];
        float4 b0 = *(const float4*)&xl[(size_t)s1 * 256 + base];
        float4 b1 = *(const float4*)&xl[(size_t)s1 * 256 + base + 4];
        float sc0 = at0.x * lrelu(a0.x + xr0.x) + at0.y * lrelu(a0.y + xr0.y)
                  + at0.z * lrelu(a0.z + xr0.z) + at0.w * lrelu(a0.w + xr0.w)
                  + at1.x * lrelu(a1.x + xr1.x) + at1.y * lrelu(a1.y + xr1.y)
                  + at1.z * lrelu(a1.z + xr1.z) + at1.w * lrelu(a1.w + xr1.w);
        float sc1 = at0.x * lrelu(b0.x + xr0.x) + at0.y * lrelu(b0.y + xr0.y)
                  + at0.z * lrelu(b0.z + xr0.z) + at0.w * lrelu(b0.w + xr0.w)
                  + at1.x * lrelu(b1.x + xr1.x) + at1.y * lrelu(b1.y + xr1.y)
                  + at1.z * lrelu(b1.z + xr1.z) + at1.w * lrelu(b1.w + xr1.w);
        sc0 += __shfl_xor_sync(0xffffffffu, sc0, 1);
        sc0 += __shfl_xor_sync(0xffffffffu, sc0, 2);
        sc1 += __shfl_xor_sync(0xffffffffu, sc1, 1);
        sc1 += __shfl_xor_sync(0xffffffffu, sc1, 2);
        float nm = fmaxf(m, fmaxf(sc0, sc1));
        float r  = __expf(m - nm);          // m=-inf -> 0
        float p0 = __expf(sc0 - nm);
        float p1 = __expf(sc1 - nm);
        d = d * r + p0 + p1;
        acc0.x = acc0.x * r + p0 * a0.x + p1 * b0.x;
        acc0.y = acc0.y * r + p0 * a0.y + p1 * b0.y;
        acc0.z = acc0.z * r + p0 * a0.z + p1 * b0.z;
        acc0.w = acc0.w * r + p0 * a0.w + p1 * b0.w;
        acc1.x = acc1.x * r + p0 * a1.x + p1 * b1.x;
        acc1.y = acc1.y * r + p0 * a1.y + p1 * b1.y;
        acc1.z = acc1.z * r + p0 * a1.z + p1 * b1.z;
        acc1.w = acc1.w * r + p0 * a1.w + p1 * b1.w;
        m = nm;
    }
    if (t < T) {                            // tail: one edge (possibly self-loop)
        int i0 = beg + t;
        int s = (i0 < end) ? g_src[i0] : node;
        float4 a0 = *(const float4*)&xl[(size_t)s * 256 + base];
        float4 a1 = *(const float4*)&xl[(size_t)s * 256 + base + 4];
        float sc = at0.x * lrelu(a0.x + xr0.x) + at0.y * lrelu(a0.y + xr0.y)
                 + at0.z * lrelu(a0.z + xr0.z) + at0.w * lrelu(a0.w + xr0.w)
                 + at1.x * lrelu(a1.x + xr1.x) + at1.y * lrelu(a1.y + xr1.y)
                 + at1.z * lrelu(a1.z + xr1.z) + at1.w * lrelu(a1.w + xr1.w);
        sc += __shfl_xor_sync(0xffffffffu, sc, 1);
        sc += __shfl_xor_sync(0xffffffffu, sc, 2);
        float nm = fmaxf(m, sc);
        float r  = __expf(m - nm);
        float p  = __expf(sc - nm);
        d = d * r + p;
        acc0.x = acc0.x * r + p * a0.x; acc0.y = acc0.y * r + p * a0.y;
        acc0.z = acc0.z * r + p * a0.z; acc0.w = acc0.w * r + p * a0.w;
        acc1.x = acc1.x * r + p * a1.x; acc1.y = acc1.y * r + p * a1.y;
        acc1.z = acc1.z * r + p * a1.z; acc1.w = acc1.w * r + p * a1.w;
    }

    float inv = 1.f / d;
    float4 b0 = *(const float4*)&bias[base];
    float4 b1 = *(const float4*)&bias[base + 4];
    float4 o0, o1;
    o0.x = elu(acc0.x * inv + b0.x); o0.y = elu(acc0.y * inv + b0.y);
    o0.z = elu(acc0.z * inv + b0.z); o0.w = elu(acc0.w * inv + b0.w);
    o1.x = elu(acc1.x * inv + b1.x); o1.y = elu(acc1.y * inv + b1.y);
    o1.z = elu(acc1.z * inv + b1.z); o1.w = elu(acc1.w * inv + b1.w);
    *(float4*)&out[(size_t)node * 256 + base]     = o0;
    *(float4*)&out[(size_t)node * 256 + base + 4] = o1;
}

// ---------------- launch ----------------
extern "C" void kernel_launch(void* const* d_in, const int* in_sizes, int n_in,
                              void* d_out, int out_size) {
    const float* x       = (const float*)d_in[0];
    const void*  ei      = d_in[1];                    // int32 or int64, detected on device
    const float* ea      = (const float*)d_in[2];
    const float* W_rel1  = (const float*)d_in[3];
    const float* b_rel1  = (const float*)d_in[4];
    const float* W_root1 = (const float*)d_in[5];
    const float* W_rel2  = (const float*)d_in[6];
    const float* b_rel2  = (const float*)d_in[7];
    const float* W_root2 = (const float*)d_in[8];
    const float* Wl1     = (const float*)d_in[9];
    const float* bl1     = (const float*)d_in[10];
    const float* Wr1     = (const float*)d_in[11];
    const float* br1     = (const float*)d_in[12];
    const float* att1    = (const float*)d_in[13];
    const float* bias1   = (const float*)d_in[14];
    const float* Wl2     = (const float*)d_in[15];
    const float* bl2     = (const float*)d_in[16];
    const float* Wr2     = (const float*)d_in[17];
    const float* br2     = (const float*)d_in[18];
    const float* att2    = (const float*)d_in[19];
    const float* bias2   = (const float*)d_in[20];
    const float* W_lin   = (const float*)d_in[21];
    const float* b_lin   = (const float*)d_in[22];
    float*       out     = (float*)d_out;

    const int M = NN;
    dim3 g256(2, (M + 127) / 128, 2);

    // dtype detection + CSR build (multi-block scan)
    k_detect<<<1, 32>>>((const int*)ei);
    k_zero_deg<<<(NN + 255) / 256, 256>>>();
    k_count<<<(NE + 255) / 256, 256>>>(ei);
    k_scan_local<<<NBLK, 1024>>>();
    k_scan_bsum<<<1, 32>>>();
    k_scan_add<<<(NN + 255) / 256, 256>>>();
    k_scatter<<<(NE + 255) / 256, 256>>>(ei, ea);

    // GraphConv 1: agg(x) -> g_bufA; h1 = relu(g_bufA@W_rel1 + x@W_root1 + b)
    k_gc_agg<128, -1><<<(NN + 7) / 8, 256>>>(x);
    k_gemm_n32<128, 0, true, -1, true, 2><<<(M + 127) / 128, 128>>>(
        (const float*)0, W_rel1, x, W_root1, b_rel1, (float*)0, M);

    // GraphConv 2: agg(h1) -> g_bufA; h2 = relu(g_bufA@W_rel2 + h1@W_root2 + b)
    k_gc_agg<32, 2><<<(NN + 7) / 8, 256>>>((const float*)0);
    k_gemm_n32<32, 0, true, 2, true, 3><<<(M + 127) / 128, 128>>>(
        (const float*)0, W_rel2, (const float*)0, W_root2, b_rel2, (float*)0, M);

    // GATv2 1: xl/xr from h2; h3 = elu(gat)
    k_gemm_n256<32, 3><<<g256, 256>>>(Wl1, bl1, Wr1, br1, M);
    k_gat<4><<<(NN + 7) / 8, 256>>>(att1, bias1);

    // GATv2 2: xl/xr from h3; h4 = elu(gat)
    k_gemm_n256<256, 4><<<g256, 256>>>(Wl2, bl2, Wr2, br2, M);
    k_gat<5><<<(NN + 7) / 8, 256>>>(att2, bias2);

    // Final linear: out = h4 @ W_lin + b_lin
    k_gemm_n32<256, 5, false, -1, false, -1><<<(M + 127) / 128, 128>>>(
        (const float*)0, W_lin, (const float*)0, (const float*)0, b_lin, out, M);
}

// round 12
// speedup vs baseline: 1.3166x; 1.2143x over previous
#include <cuda_runtime.h>
#include <cuda_bf16.h>
#include <stdint.h>
#include <math.h>

#define NN 50000
#define NE 800000
#define SCAN_CHUNK 4096
#define NBLK ((NN + SCAN_CHUNK - 1) / SCAN_CHUNK)   // 13

// ---------------- scratch (device globals: no allocation allowed) ----------
__device__ int   g_is64;
__device__ int   g_deg[NN];
__device__ int   g_off[NN + 1];
__device__ int   g_cur[NN];
__device__ int   g_bsum[NBLK];
__device__ int   g_bpre[NBLK];
__device__ int   g_src[NE];
__device__ __align__(16) float g_w[NE];
__device__ __align__(16) float g_bufA[NN * 256];   // agg128 / agg32 / xl
__device__ __align__(16) float g_bufB[NN * 256];   // xr
__device__ __align__(16) float g_h1[NN * 32];
__device__ __align__(16) float g_h2[NN * 32];
__device__ __align__(16) float g_h3[NN * 256];
__device__ __align__(16) float g_h4[NN * 256];

// Buffer selectors: resolve device-global scratch at compile time. S==-1 -> ext.
template <int S>
__device__ __forceinline__ const float* SB(const float* ext) {
    if constexpr (S == 0) return g_bufA;
    else if constexpr (S == 1) return g_bufB;
    else if constexpr (S == 2) return g_h1;
    else if constexpr (S == 3) return g_h2;
    else if constexpr (S == 4) return g_h3;
    else if constexpr (S == 5) return g_h4;
    else return ext;
}
template <int S>
__device__ __forceinline__ float* SBo(float* ext) {
    if constexpr (S == 0) return g_bufA;
    else if constexpr (S == 1) return g_bufB;
    else if constexpr (S == 2) return g_h1;
    else if constexpr (S == 3) return g_h2;
    else if constexpr (S == 4) return g_h3;
    else if constexpr (S == 5) return g_h4;
    else return ext;
}

// ---------------- helpers ----------------
__device__ __forceinline__ float lrelu(float v) { return v > 0.f ? v : 0.2f * v; }
__device__ __forceinline__ float elu(float v)  { return v > 0.f ? v : __expf(v) - 1.f; }

__device__ __forceinline__ int clampN(int v) {
    return v < 0 ? 0 : (v >= NN ? NN - 1 : v);
}
__device__ __forceinline__ int load_idx(const void* ei, size_t pos, int is64) {
    if (is64) return clampN((int)((const long long*)ei)[pos]);
    return clampN(((const int*)ei)[pos]);
}

static __device__ __forceinline__ uint32_t pack2(__nv_bfloat16 a, __nv_bfloat16 b) {
    return (uint32_t)__bfloat16_as_ushort(a) | ((uint32_t)__bfloat16_as_ushort(b) << 16);
}

// mma.sync m16n8k16 row.col f32.bf16.bf16.f32 (legacy tensor path, sm_80+)
#define MMA_BF16(d, a, b0v, b1v) \
    asm volatile("mma.sync.aligned.m16n8k16.row.col.f32.bf16.bf16.f32 " \
        "{%0,%1,%2,%3}, {%4,%5,%6,%7}, {%8,%9}, {%0,%1,%2,%3};" \
        : "+f"((d)[0]), "+f"((d)[1]), "+f"((d)[2]), "+f"((d)[3]) \
        : "r"((a)[0]), "r"((a)[1]), "r"((a)[2]), "r"((a)[3]), "r"(b0v), "r"(b1v))

// ---------------- dtype detection ----------------
__global__ void k_detect(const int* __restrict__ ei32) {
    if (threadIdx.x == 0 && blockIdx.x == 0) {
        int allzero = 1;
        #pragma unroll 1
        for (int i = 0; i < 64; i++)
            if (ei32[2 * i + 1] != 0) { allzero = 0; break; }
        g_is64 = allzero;
    }
}

// ---------------- CSR build ----------------
__global__ void k_zero_deg() {
    int i = blockIdx.x * blockDim.x + threadIdx.x;
    if (i < NN) g_deg[i] = 0;
}

__global__ void k_count(const void* __restrict__ ei) {
    int e = blockIdx.x * blockDim.x + threadIdx.x;
    if (e < NE) {
        int dst = load_idx(ei, (size_t)NE + e, g_is64);
        atomicAdd(&g_deg[dst], 1);
    }
}

__global__ __launch_bounds__(1024) void k_scan_local() {
    __shared__ int ws[32];
    int b = blockIdx.x, t = threadIdx.x;
    int base = b * SCAN_CHUNK + t * 4;
    int v[4];
    #pragma unroll
    for (int c = 0; c < 4; c++) v[c] = (base + c < NN) ? g_deg[base + c] : 0;
    int s = v[0] + v[1] + v[2] + v[3];
    int x = s;
    #pragma unroll
    for (int o = 1; o < 32; o <<= 1) {
        int y = __shfl_up_sync(0xffffffffu, x, o);
        if ((t & 31) >= o) x += y;
    }
    if ((t & 31) == 31) ws[t >> 5] = x;
    __syncthreads();
    if (t < 32) {
        int w = ws[t];
        #pragma unroll
        for (int o = 1; o < 32; o <<= 1) {
            int y = __shfl_up_sync(0xffffffffu, w, o);
            if (t >= o) w += y;
        }
        ws[t] = w;
    }
    __syncthreads();
    int incl = x + ((t >= 32) ? ws[(t >> 5) - 1] : 0);
    int run = incl - s;
    #pragma unroll
    for (int c = 0; c < 4; c++) {
        if (base + c < NN) g_off[base + c] = run;
        run += v[c];
    }
    if (t == 1023) g_bsum[b] = incl;
}

__global__ void k_scan_bsum() {
    int t = threadIdx.x;
    int v = (t < NBLK) ? g_bsum[t] : 0;
    int x = v;
    #pragma unroll
    for (int o = 1; o < 32; o <<= 1) {
        int y = __shfl_up_sync(0xffffffffu, x, o);
        if (t >= o) x += y;
    }
    if (t < NBLK) g_bpre[t] = x - v;
    if (t == 31) g_off[NN] = x;
}

__global__ void k_scan_add() {
    int i = blockIdx.x * blockDim.x + threadIdx.x;
    if (i < NN) {
        int o = g_off[i] + g_bpre[i / SCAN_CHUNK];
        g_off[i] = o;
        g_cur[i] = o;
    }
}

__global__ void k_scatter(const void* __restrict__ ei, const float* __restrict__ ea) {
    int e = blockIdx.x * blockDim.x + threadIdx.x;
    if (e < NE) {
        int is64 = g_is64;
        int s = load_idx(ei, (size_t)e, is64);
        int d = load_idx(ei, (size_t)NE + e, is64);
        int p = atomicAdd(&g_cur[d], 1);
        if (p >= 0 && p < NE) {
            g_src[p] = s;
            g_w[p]   = ea[e];
        }
    }
}

// ---------------- GraphConv max aggregation (warp per node, unroll-4) ------
template <int F, int XSEL>
__global__ void k_gc_agg(const float* __restrict__ xext) {
    const float* __restrict__ x = SB<XSEL>(xext);
    float* __restrict__ agg = g_bufA;
    int node = (blockIdx.x * blockDim.x + threadIdx.x) >> 5;
    int lane = threadIdx.x & 31;
    if (node >= NN) return;
    int beg = g_off[node], end = g_off[node + 1];
    if constexpr (F == 128) {
        float4 mx = make_float4(-INFINITY, -INFINITY, -INFINITY, -INFINITY);
        int j = beg;
        for (; j + 3 < end; j += 4) {
            int   s0 = g_src[j],   s1 = g_src[j+1], s2 = g_src[j+2], s3 = g_src[j+3];
            float w0 = g_w[j],     w1 = g_w[j+1],   w2 = g_w[j+2],   w3 = g_w[j+3];
            float4 v0 = *(const float4*)&x[(size_t)s0 * 128 + lane * 4];
            float4 v1 = *(const float4*)&x[(size_t)s1 * 128 + lane * 4];
            float4 v2 = *(const float4*)&x[(size_t)s2 * 128 + lane * 4];
            float4 v3 = *(const float4*)&x[(size_t)s3 * 128 + lane * 4];
            mx.x = fmaxf(mx.x, fmaxf(fmaxf(v0.x*w0, v1.x*w1), fmaxf(v2.x*w2, v3.x*w3)));
            mx.y = fmaxf(mx.y, fmaxf(fmaxf(v0.y*w0, v1.y*w1), fmaxf(v2.y*w2, v3.y*w3)));
            mx.z = fmaxf(mx.z, fmaxf(fmaxf(v0.z*w0, v1.z*w1), fmaxf(v2.z*w2, v3.z*w3)));
            mx.w = fmaxf(mx.w, fmaxf(fmaxf(v0.w*w0, v1.w*w1), fmaxf(v2.w*w2, v3.w*w3)));
        }
        for (; j < end; j++) {
            int s = g_src[j];
            float w = g_w[j];
            float4 v = *(const float4*)&x[(size_t)s * 128 + lane * 4];
            mx.x = fmaxf(mx.x, v.x * w);
            mx.y = fmaxf(mx.y, v.y * w);
            mx.z = fmaxf(mx.z, v.z * w);
            mx.w = fmaxf(mx.w, v.w * w);
        }
        if (beg == end) mx = make_float4(0.f, 0.f, 0.f, 0.f);
        *(float4*)&agg[(size_t)node * 128 + lane * 4] = mx;
    } else {
        float mx = -INFINITY;
        int j = beg;
        for (; j + 3 < end; j += 4) {
            int   s0 = g_src[j],   s1 = g_src[j+1], s2 = g_src[j+2], s3 = g_src[j+3];
            float w0 = g_w[j],     w1 = g_w[j+1],   w2 = g_w[j+2],   w3 = g_w[j+3];
            float a = x[(size_t)s0 * 32 + lane] * w0;
            float b = x[(size_t)s1 * 32 + lane] * w1;
            float c = x[(size_t)s2 * 32 + lane] * w2;
            float d = x[(size_t)s3 * 32 + lane] * w3;
            mx = fmaxf(mx, fmaxf(fmaxf(a, b), fmaxf(c, d)));
        }
        for (; j < end; j++) mx = fmaxf(mx, x[(size_t)g_src[j] * 32 + lane] * g_w[j]);
        agg[(size_t)node * 32 + lane] = (beg == end) ? 0.f : mx;
    }
}

// ---------------- GEMM, N-out = 32 (fp32; GC layers + final linear) -------
template <int K, int A1SEL, bool DUAL, int A2SEL, bool RELU, int CSEL>
__global__ __launch_bounds__(128)
void k_gemm_n32(const float* __restrict__ A1e, const float* __restrict__ B1,
                const float* __restrict__ A2e, const float* __restrict__ B2,
                const float* __restrict__ bias, float* __restrict__ Ce, int M) {
    const float* __restrict__ A1 = SB<A1SEL>(A1e);
    const float* __restrict__ A2 = SB<A2SEL>(A2e);
    float* __restrict__ C = SBo<CSEL>(Ce);

    __shared__ float As[32][128];
    __shared__ float A2s[32][128];
    __shared__ float Bs[32][32];
    __shared__ float B2s[32][32];

    int t  = threadIdx.x;
    int m0 = blockIdx.x * 128;
    int j0 = (t & 7) * 4;
    int r0 = (t >> 3) * 8;

    float acc[8][4];
    #pragma unroll
    for (int i = 0; i < 8; i++)
        #pragma unroll
        for (int c = 0; c < 4; c++) acc[i][c] = 0.f;

    for (int kb = 0; kb < K; kb += 32) {
        #pragma unroll
        for (int l = 0; l < 8; l++) {
            int slot = t + l * 128;
            int m = slot >> 3;
            int kq = slot & 7;
            int row = m0 + m;
            float4 v = make_float4(0.f, 0.f, 0.f, 0.f);
            if (row < M) v = *(const float4*)&A1[(size_t)row * K + kb + kq * 4];
            As[kq * 4 + 0][m] = v.x; As[kq * 4 + 1][m] = v.y;
            As[kq * 4 + 2][m] = v.z; As[kq * 4 + 3][m] = v.w;
            if constexpr (DUAL) {
                float4 v2 = make_float4(0.f, 0.f, 0.f, 0.f);
                if (row < M) v2 = *(const float4*)&A2[(size_t)row * K + kb + kq * 4];
                A2s[kq * 4 + 0][m] = v2.x; A2s[kq * 4 + 1][m] = v2.y;
                A2s[kq * 4 + 2][m] = v2.z; A2s[kq * 4 + 3][m] = v2.w;
            }
        }
        #pragma unroll
        for (int l = 0; l < 2; l++) {
            int slot = t + l * 128;
            int k = slot >> 3;
            int jq = slot & 7;
            *(float4*)&Bs[k][jq * 4] = *(const float4*)&B1[(size_t)(kb + k) * 32 + jq * 4];
            if constexpr (DUAL)
                *(float4*)&B2s[k][jq * 4] = *(const float4*)&B2[(size_t)(kb + k) * 32 + jq * 4];
        }
        __syncthreads();

        #pragma unroll
        for (int kk = 0; kk < 32; kk++) {
            float av[8], bv[4];
            *(float4*)&av[0] = *(float4*)&As[kk][r0];
            *(float4*)&av[4] = *(float4*)&As[kk][r0 + 4];
            *(float4*)&bv[0] = *(float4*)&Bs[kk][j0];
            #pragma unroll
            for (int i = 0; i < 8; i++)
                #pragma unroll
                for (int c = 0; c < 4; c++) acc[i][c] += av[i] * bv[c];
            if constexpr (DUAL) {
                float av2[8], bv2[4];
                *(float4*)&av2[0] = *(float4*)&A2s[kk][r0];
                *(float4*)&av2[4] = *(float4*)&A2s[kk][r0 + 4];
                *(float4*)&bv2[0] = *(float4*)&B2s[kk][j0];
                #pragma unroll
                for (int i = 0; i < 8; i++)
                    #pragma unroll
                    for (int c = 0; c < 4; c++) acc[i][c] += av2[i] * bv2[c];
            }
        }
        __syncthreads();
    }

    float bv[4];
    *(float4*)&bv[0] = *(const float4*)&bias[j0];
    #pragma unroll
    for (int i = 0; i < 8; i++) {
        int row = m0 + r0 + i;
        if (row < M) {
            float o[4];
            #pragma unroll
            for (int c = 0; c < 4; c++) {
                float v = acc[i][c] + bv[c];
                if constexpr (RELU) v = fmaxf(v, 0.f);
                o[c] = v;
            }
            *(float4*)&C[(size_t)row * 32 + j0] = *(float4*)&o[0];
        }
    }
}

// ---------------- mma.sync bf16 GEMM: xl/xr (N=256), 3-term split ----------
// C[M,256] = A[M,KDIM] @ W (+bias); z=0 -> Wl/g_bufA, z=1 -> Wr/g_bufB.
// A,W split into bf16 hi+lo; D += Ahi*Whi + Ahi*Wlo + Alo*Whi (fp32 acc).
// Block 256 thr (8 warps, 4m x 2n), tile 128x128, BK=32.
template <int KDIM, int ASEL>
__global__ __launch_bounds__(256)
void k_mma_gemm(const float* __restrict__ Bl, const float* __restrict__ biasl,
                const float* __restrict__ Br, const float* __restrict__ biasr) {
    constexpr int KW = 16;                      // BK/2 words per row
    __shared__ uint32_t Ah[128][KW + 1], Al[128][KW + 1];
    __shared__ uint32_t Bh[128][KW + 1], Bq[128][KW + 1];

    const float* __restrict__ A = SB<ASEL>((const float*)0);
    const float* __restrict__ W  = blockIdx.z ? Br : Bl;
    const float* __restrict__ bi = blockIdx.z ? biasr : biasl;
    float* __restrict__ C        = blockIdx.z ? g_bufB : g_bufA;

    int tid = threadIdx.x;
    int wid = tid >> 5, lane = tid & 31;
    int warp_m = wid & 3, warp_n = wid >> 2;
    int m0 = blockIdx.y * 128;
    int n0 = blockIdx.x * 128;
    int lg = lane >> 2, lq = lane & 3;          // group row / quad

    float acc[2][8][4];
    #pragma unroll
    for (int mt = 0; mt < 2; mt++)
        #pragma unroll
        for (int nt = 0; nt < 8; nt++)
            #pragma unroll
            for (int c = 0; c < 4; c++) acc[mt][nt][c] = 0.f;

    for (int kb = 0; kb < KDIM; kb += 32) {
        // load A tile (128 rows x 16 words), convert fp32 -> bf16 hi/lo
        #pragma unroll
        for (int i = 0; i < 8; i++) {
            int idx = tid + i * 256;            // 0..2047
            int r = idx >> 4, w = idx & 15;
            int row = m0 + r;
            float2 u = make_float2(0.f, 0.f);
            if (row < NN) u = ((const float2*)&A[(size_t)row * KDIM + kb])[w];
            __nv_bfloat16 hx = __float2bfloat16(u.x);
            __nv_bfloat16 hy = __float2bfloat16(u.y);
            Ah[r][w] = pack2(hx, hy);
            Al[r][w] = pack2(__float2bfloat16(u.x - __bfloat162float(hx)),
                             __float2bfloat16(u.y - __bfloat162float(hy)));
        }
        // load W tile: Bh[n][w] = W[kb+2w][n0+n], W[kb+2w+1][n0+n]
        #pragma unroll
        for (int i = 0; i < 8; i++) {
            int idx = tid + i * 256;
            int n = idx & 127, w = idx >> 7;
            int k0 = kb + w * 2;
            float v0 = W[(size_t)k0 * 256 + n0 + n];
            float v1 = W[(size_t)(k0 + 1) * 256 + n0 + n];
            __nv_bfloat16 h0 = __float2bfloat16(v0);
            __nv_bfloat16 h1 = __float2bfloat16(v1);
            Bh[n][w] = pack2(h0, h1);
            Bq[n][w] = pack2(__float2bfloat16(v0 - __bfloat162float(h0)),
                             __float2bfloat16(v1 - __bfloat162float(h1)));
        }
        __syncthreads();

        #pragma unroll
        for (int ks = 0; ks < 2; ks++) {
            int ws = ks * 8;
            uint32_t ah[2][4], al[2][4];
            #pragma unroll
            for (int mt = 0; mt < 2; mt++) {
                int r = warp_m * 32 + mt * 16 + lg;
                ah[mt][0] = Ah[r][ws + lq];     ah[mt][1] = Ah[r + 8][ws + lq];
                ah[mt][2] = Ah[r][ws + 4 + lq]; ah[mt][3] = Ah[r + 8][ws + 4 + lq];
                al[mt][0] = Al[r][ws + lq];     al[mt][1] = Al[r + 8][ws + lq];
                al[mt][2] = Al[r][ws + 4 + lq]; al[mt][3] = Al[r + 8][ws + 4 + lq];
            }
            #pragma unroll
            for (int nt = 0; nt < 8; nt++) {
                int cb = warp_n * 64 + nt * 8 + lg;
                uint32_t bh0 = Bh[cb][ws + lq], bh1 = Bh[cb][ws + 4 + lq];
                uint32_t bq0 = Bq[cb][ws + lq], bq1 = Bq[cb][ws + 4 + lq];
                #pragma unroll
                for (int mt = 0; mt < 2; mt++) {
                    MMA_BF16(acc[mt][nt], ah[mt], bh0, bh1);
                    MMA_BF16(acc[mt][nt], ah[mt], bq0, bq1);
                    MMA_BF16(acc[mt][nt], al[mt], bh0, bh1);
                }
            }
        }
        __syncthreads();
    }

    // epilogue: add bias, store
    #pragma unroll
    for (int nt = 0; nt < 8; nt++) {
        int col = n0 + warp_n * 64 + nt * 8 + lq * 2;
        float b0 = bi[col], b1 = bi[col + 1];
        #pragma unroll
        for (int mt = 0; mt < 2; mt++) {
            int r0 = m0 + warp_m * 32 + mt * 16 + lg;
            if (r0 < NN) {
                float2 o = make_float2(acc[mt][nt][0] + b0, acc[mt][nt][1] + b1);
                *(float2*)&C[(size_t)r0 * 256 + col] = o;
            }
            if (r0 + 8 < NN) {
                float2 o = make_float2(acc[mt][nt][2] + b0, acc[mt][nt][3] + b1);
                *(float2*)&C[(size_t)(r0 + 8) * 256 + col] = o;
            }
        }
    }
}

// ---------------- GATv2: warp per node, 2-edge branch-free online softmax --
template <int OSEL>
__global__ void k_gat(const float* __restrict__ att, const float* __restrict__ bias) {
    const float* __restrict__ xl = g_bufA;
    const float* __restrict__ xr = g_bufB;
    float* __restrict__ out = SBo<OSEL>((float*)0);

    int node = (blockIdx.x * blockDim.x + threadIdx.x) >> 5;
    int lane = threadIdx.x & 31;
    if (node >= NN) return;
    int base = (lane >> 2) * 32 + (lane & 3) * 8;

    float4 at0 = *(const float4*)&att[base];
    float4 at1 = *(const float4*)&att[base + 4];
    float4 xr0 = *(const float4*)&xr[(size_t)node * 256 + base];
    float4 xr1 = *(const float4*)&xr[(size_t)node * 256 + base + 4];

    float m = -INFINITY, d = 0.f;
    float4 acc0 = make_float4(0.f, 0.f, 0.f, 0.f);
    float4 acc1 = make_float4(0.f, 0.f, 0.f, 0.f);

    int beg = g_off[node], end = g_off[node + 1];
    int T = end - beg + 1;
    int t = 0;
    for (; t + 1 < T; t += 2) {
        int i0 = beg + t, i1 = beg + t + 1;
        int s0 = g_src[i0];
        int s1 = (i1 < end) ? g_src[i1] : node;
        float4 a0 = *(const float4*)&xl[(size_t)s0 * 256 + base];
        float4 a1 = *(const float4*)&xl[(size_t)s0 * 256 + base + 4];
        float4 b0 = *(const float4*)&xl[(size_t)s1 * 256 + base];
        float4 b1 = *(const float4*)&xl[(size_t)s1 * 256 + base + 4];
        float sc0 = at0.x * lrelu(a0.x + xr0.x) + at0.y * lrelu(a0.y + xr0.y)
                  + at0.z * lrelu(a0.z + xr0.z) + at0.w * lrelu(a0.w + xr0.w)
                  + at1.x * lrelu(a1.x + xr1.x) + at1.y * lrelu(a1.y + xr1.y)
                  + at1.z * lrelu(a1.z + xr1.z) + at1.w * lrelu(a1.w + xr1.w);
        float sc1 = at0.x * lrelu(b0.x + xr0.x) + at0.y * lrelu(b0.y + xr0.y)
                  + at0.z * lrelu(b0.z + xr0.z) + at0.w * lrelu(b0.w + xr0.w)
                  + at1.x * lrelu(b1.x + xr1.x) + at1.y * lrelu(b1.y + xr1.y)
                  + at1.z * lrelu(b1.z + xr1.z) + at1.w * lrelu(b1.w + xr1.w);
        sc0 += __shfl_xor_sync(0xffffffffu, sc0, 1);
        sc0 += __shfl_xor_sync(0xffffffffu, sc0, 2);
        sc1 += __shfl_xor_sync(0xffffffffu, sc1, 1);
        sc1 += __shfl_xor_sync(0xffffffffu, sc1, 2);
        float nm = fmaxf(m, fmaxf(sc0, sc1));
        float r  = __expf(m - nm);
        float p0 = __expf(sc0 - nm);
        float p1 = __expf(sc1 - nm);
        d = d * r + p0 + p1;
        acc0.x = acc0.x * r + p0 * a0.x + p1 * b0.x;
        acc0.y = acc0.y * r + p0 * a0.y + p1 * b0.y;
        acc0.z = acc0.z * r + p0 * a0.z + p1 * b0.z;
        acc0.w = acc0.w * r + p0 * a0.w + p1 * b0.w;
        acc1.x = acc1.x * r + p0 * a1.x + p1 * b1.x;
        acc1.y = acc1.y * r + p0 * a1.y + p1 * b1.y;
        acc1.z = acc1.z * r + p0 * a1.z + p1 * b1.z;
        acc1.w = acc1.w * r + p0 * a1.w + p1 * b1.w;
        m = nm;
    }
    if (t < T) {
        int i0 = beg + t;
        int s = (i0 < end) ? g_src[i0] : node;
        float4 a0 = *(const float4*)&xl[(size_t)s * 256 + base];
        float4 a1 = *(const float4*)&xl[(size_t)s * 256 + base + 4];
        float sc = at0.x * lrelu(a0.x + xr0.x) + at0.y * lrelu(a0.y + xr0.y)
                 + at0.z * lrelu(a0.z + xr0.z) + at0.w * lrelu(a0.w + xr0.w)
                 + at1.x * lrelu(a1.x + xr1.x) + at1.y * lrelu(a1.y + xr1.y)
                 + at1.z * lrelu(a1.z + xr1.z) + at1.w * lrelu(a1.w + xr1.w);
        sc += __shfl_xor_sync(0xffffffffu, sc, 1);
        sc += __shfl_xor_sync(0xffffffffu, sc, 2);
        float nm = fmaxf(m, sc);
        float r  = __expf(m - nm);
        float p  = __expf(sc - nm);
        d = d * r + p;
        acc0.x = acc0.x * r + p * a0.x; acc0.y = acc0.y * r + p * a0.y;
        acc0.z = acc0.z * r + p * a0.z; acc0.w = acc0.w * r + p * a0.w;
        acc1.x = acc1.x * r + p * a1.x; acc1.y = acc1.y * r + p * a1.y;
        acc1.z = acc1.z * r + p * a1.z; acc1.w = acc1.w * r + p * a1.w;
    }

    float inv = 1.f / d;
    float4 b0 = *(const float4*)&bias[base];
    float4 b1 = *(const float4*)&bias[base + 4];
    float4 o0, o1;
    o0.x = elu(acc0.x * inv + b0.x); o0.y = elu(acc0.y * inv + b0.y);
    o0.z = elu(acc0.z * inv + b0.z); o0.w = elu(acc0.w * inv + b0.w);
    o1.x = elu(acc1.x * inv + b1.x); o1.y = elu(acc1.y * inv + b1.y);
    o1.z = elu(acc1.z * inv + b1.z); o1.w = elu(acc1.w * inv + b1.w);
    *(float4*)&out[(size_t)node * 256 + base]     = o0;
    *(float4*)&out[(size_t)node * 256 + base + 4] = o1;
}

// ---------------- launch ----------------
extern "C" void kernel_launch(void* const* d_in, const int* in_sizes, int n_in,
                              void* d_out, int out_size) {
    const float* x       = (const float*)d_in[0];
    const void*  ei      = d_in[1];
    const float* ea      = (const float*)d_in[2];
    const float* W_rel1  = (const float*)d_in[3];
    const float* b_rel1  = (const float*)d_in[4];
    const float* W_root1 = (const float*)d_in[5];
    const float* W_rel2  = (const float*)d_in[6];
    const float* b_rel2  = (const float*)d_in[7];
    const float* W_root2 = (const float*)d_in[8];
    const float* Wl1     = (const float*)d_in[9];
    const float* bl1     = (const float*)d_in[10];
    const float* Wr1     = (const float*)d_in[11];
    const float* br1     = (const float*)d_in[12];
    const float* att1    = (const float*)d_in[13];
    const float* bias1   = (const float*)d_in[14];
    const float* Wl2     = (const float*)d_in[15];
    const float* bl2     = (const float*)d_in[16];
    const float* Wr2     = (const float*)d_in[17];
    const float* br2     = (const float*)d_in[18];
    const float* att2    = (const float*)d_in[19];
    const float* bias2   = (const float*)d_in[20];
    const float* W_lin   = (const float*)d_in[21];
    const float* b_lin   = (const float*)d_in[22];
    float*       out     = (float*)d_out;

    const int M = NN;
    const int MT = (M + 127) / 128;   // 391 M-tiles
    dim3 gmma(2, MT, 2);

    // dtype detection + CSR build
    k_detect<<<1, 32>>>((const int*)ei);
    k_zero_deg<<<(NN + 255) / 256, 256>>>();
    k_count<<<(NE + 255) / 256, 256>>>(ei);
    k_scan_local<<<NBLK, 1024>>>();
    k_scan_bsum<<<1, 32>>>();
    k_scan_add<<<(NN + 255) / 256, 256>>>();
    k_scatter<<<(NE + 255) / 256, 256>>>(ei, ea);

    // GraphConv 1
    k_gc_agg<128, -1><<<(NN + 7) / 8, 256>>>(x);
    k_gemm_n32<128, 0, true, -1, true, 2><<<MT, 128>>>(
        (const float*)0, W_rel1, x, W_root1, b_rel1, (float*)0, M);

    // GraphConv 2
    k_gc_agg<32, 2><<<(NN + 7) / 8, 256>>>((const float*)0);
    k_gemm_n32<32, 0, true, 2, true, 3><<<MT, 128>>>(
        (const float*)0, W_rel2, (const float*)0, W_root2, b_rel2, (float*)0, M);

    // GATv2 1: xl/xr via mma.sync bf16-split (A = h2, K=32)
    k_mma_gemm<32, 3><<<gmma, 256>>>(Wl1, bl1, Wr1, br1);
    k_gat<4><<<(NN + 7) / 8, 256>>>(att1, bias1);

    // GATv2 2: xl/xr via mma.sync bf16-split (A = h3, K=256)
    k_mma_gemm<256, 4><<<gmma, 256>>>(Wl2, bl2, Wr2, br2);
    k_gat<5><<<(NN + 7) / 8, 256>>>(att2, bias2);

    // Final linear
    k_gemm_n32<256, 5, false, -1, false, -1><<<MT, 128>>>(
        (const float*)0, W_lin, (const float*)0, (const float*)0, b_lin, out, M);
}